// round 4
// baseline (speedup 1.0000x reference)
#include <cuda_runtime.h>
#include <math.h>

// B=2, C=32, H=512, W=512, SCALE=2 -> Hs=Ws=256, S2=4
// Key fact: argsort indices form a permutation of {0..3} per pixel -> only 24
// distinct per-pixel codes. ifft2 is linear, so per (b,c):
//   ifft2(X_bc) = sum_p Cp[bc][p] * M_p,  M_p = ifft2(indicator(perm==p))
// Only 24 mask IFFTs needed (shared across all 64 (b,c) images).

// ---------------- scratch ----------------
__device__ float         d_Fpart[2 * 8 * 8];
__device__ float2        d_F[2 * 4];
__device__ float         d_TR[2 * 32 * 4 * 4];
__device__ float         d_TI[2 * 32 * 4 * 4];
__device__ float2        d_Cp[64 * 24];            // combined value per (bc, perm)
__device__ unsigned char d_ppix[256 * 256];        // per-pixel perm index [0,24)
__device__ unsigned char d_code2p[256];            // byte-code -> perm index
__device__ float2        d_tw[128];                // exp(+2*pi*i*t/256)
__device__ float2        d_Ym[24 * 256 * 256];     // mask row-IFFT intermediate (12.6MB)
__device__ float2        d_M[24 * 256 * 256];      // mask 2D IFFT (12.6MB)

// permutation unranking (factorial number system), code packs elems at 2-bit fields
__device__ __forceinline__ int perm_code(int p) {
    int avail[4] = {0, 1, 2, 3};
    const int f[3] = {6, 2, 1};
    int code = 0, rem = p;
#pragma unroll
    for (int pos = 0; pos < 3; pos++) {
        int sel = rem / f[pos];
        rem -= sel * f[pos];
        int e = avail[sel];
#pragma unroll
        for (int q = 0; q < 3; q++)
            if (q >= sel) avail[q] = avail[q + 1];
        code |= e << (2 * pos);
    }
    code |= avail[0] << 6;
    return code;
}

// ---------------- K0: partial sums for F[b,t] (channel 0 only) ----------------
__global__ void k0_colpart(const float* __restrict__ x) {
    int b = blockIdx.y;
    int hb = blockIdx.x;
    int w = threadIdx.x;
    const float* xp = x + (size_t)b * 32 * 512 * 512 + (size_t)(hb * 64) * 512 + w;
    float s = 0.f;
#pragma unroll 8
    for (int h = 0; h < 64; h++) s += xp[(size_t)h * 512];

    float vals[8];
#pragma unroll
    for (int t = 0; t < 4; t++) {
        float ph = (float)(t * w) * (1.0f / 256.0f);
        float sn, cs;
        sincospif(ph, &sn, &cs);
        vals[2 * t] = s * cs;
        vals[2 * t + 1] = -s * sn;
    }
    unsigned lane = threadIdx.x & 31, wid = threadIdx.x >> 5;
#pragma unroll
    for (int v = 0; v < 8; v++)
#pragma unroll
        for (int off = 16; off; off >>= 1)
            vals[v] += __shfl_down_sync(0xffffffff, vals[v], off);

    __shared__ float wsum[16][8];
    if (lane == 0)
        for (int v = 0; v < 8; v++) wsum[wid][v] = vals[v];
    __syncthreads();
    if (threadIdx.x == 0) {
        for (int v = 0; v < 8; v++) {
            float a = 0.f;
            for (int k = 0; k < 16; k++) a += wsum[k][v];
            d_Fpart[(b * 8 + hb) * 8 + v] = a;
        }
    }
}

// ---------------- K1: reduce F, build MLP tables ----------------
__global__ void k1_tables(const float* __restrict__ w1r, const float* __restrict__ b1r,
                          const float* __restrict__ w2r, const float* __restrict__ b2r,
                          const float* __restrict__ w1i, const float* __restrict__ b1i,
                          const float* __restrict__ w2i, const float* __restrict__ b2i) {
    __shared__ float2 sF[8];
    int tid = threadIdx.x;
    if (tid < 8) {
        int b = tid >> 2, k = tid & 3;
        float re = 0.f, im = 0.f;
        for (int hb = 0; hb < 8; hb++) {
            re += d_Fpart[(b * 8 + hb) * 8 + 2 * k];
            im += d_Fpart[(b * 8 + hb) * 8 + 2 * k + 1];
        }
        sF[tid] = make_float2(re, im);
        d_F[tid] = sF[tid];
    }
    __syncthreads();

    for (int e = tid; e < 2048; e += 256) {
        int isI = e >> 10;
        int r = e & 1023;
        int b = r >> 9;
        int g = (r >> 4) & 31;
        int o = (r >> 2) & 3;
        int k = r & 3;
        const float* w1 = isI ? w1i : w1r;
        const float* b1 = isI ? b1i : b1r;
        const float* w2 = isI ? w2i : w2r;
        const float* b2 = isI ? b2i : b2r;
        float v = isI ? sF[b * 4 + k].y : sF[b * 4 + k].x;
        float h[4];
#pragma unroll
        for (int ii = 0; ii < 4; ii++) {
            const float* wrow = w1 + (g * 4 + ii) * 4;
            float ws = wrow[0] + wrow[1] + wrow[2] + wrow[3];
            float y = v * ws + b1[g * 4 + ii];
            h[ii] = y > 0.f ? y : 0.1f * y;
        }
        float out = b2[g * 4 + o];
#pragma unroll
        for (int ii = 0; ii < 4; ii++) out += w2[(g * 4 + o) * 4 + ii] * h[ii];
        (isI ? d_TI : d_TR)[((b * 32 + g) * 4 + o) * 4 + k] = out;
    }
}

// ---------------- K2: Cp[bc][p] for the 24 permutations ----------------
__global__ void k2_cp() {
    int bc = blockIdx.x;
    int b = bc >> 5, Cc = bc & 31;
    __shared__ float swr[4][4], swi[4][4];
    __shared__ float2 sFv[4];
    int tid = threadIdx.x;  // 64
    if (tid < 32) {
        int P = tid >> 3, kk = (tid >> 1) & 3, ri = tid & 1;
        int g = 8 * P + (Cc >> 2), o = Cc & 3;
        float v = (ri ? d_TI : d_TR)[((b * 32 + g) * 4 + o) * 4 + kk];
        if (ri) swi[P][kk] = v; else swr[P][kk] = v;
    } else if (tid < 36) {
        sFv[tid - 32] = d_F[b * 4 + (tid - 32)];
    }
    __syncthreads();

    if (tid < 24) {
        int code = perm_code(tid);
        int ks[4] = { code & 3, (code >> 2) & 3, (code >> 4) & 3, (code >> 6) & 3 };
        float ar[4], ai[4];
#pragma unroll
        for (int P = 0; P < 4; P++) { ar[P] = swr[P][ks[P]]; ai[P] = swi[P][ks[P]]; }
        float mr = fmaxf(fmaxf(ar[0], ar[1]), fmaxf(ar[2], ar[3]));
        float mi = fmaxf(fmaxf(ai[0], ai[1]), fmaxf(ai[2], ai[3]));
        float er[4], ei_[4], sre = 0.f, sie = 0.f;
#pragma unroll
        for (int P = 0; P < 4; P++) {
            er[P] = __expf(ar[P] - mr); sre += er[P];
            ei_[P] = __expf(ai[P] - mi); sie += ei_[P];
        }
        float rinv = 1.f / sre, iinv = 1.f / sie;
        float Cr = 0.f, Ci = 0.f;
#pragma unroll
        for (int P = 0; P < 4; P++) {
            float sr = er[P] * rinv, si = ei_[P] * iinv;
            float fr = sFv[ks[P]].x, fi = sFv[ks[P]].y;
            Cr += fr * sr - fi * si;
            Ci += fr * si + fi * sr;
        }
        d_Cp[bc * 24 + tid] = make_float2(Cr * (1.f / 65536.f), Ci * (1.f / 65536.f));
    }
}

// ---------------- Klut: code -> perm index ----------------
__global__ void klut() {
    int t = threadIdx.x;
    if (t < 24) d_code2p[perm_code(t)] = (unsigned char)t;
}

// ---------------- K3: per-pixel perm index ----------------
__global__ void k3_pix(const int* __restrict__ ei) {
    int pix = blockIdx.x * 256 + threadIdx.x;
    unsigned code = 0;
#pragma unroll
    for (int P = 0; P < 4; P++)
        code |= ((unsigned)ei[(size_t)P * 2097152 + pix] & 3u) << (2 * P);
    d_ppix[pix] = d_code2p[code];
}

// ---------------- K4: twiddles exp(+2*pi*i*t/256) ----------------
__global__ void k4_tw() {
    int t = threadIdx.x;
    float sn, cs;
    sincospif((float)t * (1.0f / 128.0f), &sn, &cs);
    d_tw[t] = make_float2(cs, sn);
}

// ---------------- K5m: mask row IFFT (radix-2 Stockham, inverse) ----------------
__global__ void k5m_row() {
    __shared__ float2 bufA[256], bufB[256];
    __shared__ float2 tw[128];
    int p = blockIdx.x >> 8;
    int i = blockIdx.x & 255;
    int t = threadIdx.x;  // 128

    tw[t] = d_tw[t];
    unsigned char id0 = d_ppix[i * 256 + t];
    unsigned char id1 = d_ppix[i * 256 + t + 128];
    bufA[t] = make_float2(id0 == p ? 1.f : 0.f, 0.f);
    bufA[t + 128] = make_float2(id1 == p ? 1.f : 0.f, 0.f);
    __syncthreads();

    float2* A = bufA;
    float2* Bf = bufB;
#pragma unroll
    for (int s = 0; s < 8; s++) {
        int m1 = (1 << s) - 1;
        int k = t & m1;
        int jm = t - k;
        float2 c0 = A[t];
        float2 c1 = A[t + 128];
        float2 w = tw[jm];
        float dr = c0.x - c1.x, di = c0.y - c1.y;
        int lo = 2 * jm + k;
        Bf[lo] = make_float2(c0.x + c1.x, c0.y + c1.y);
        Bf[lo + m1 + 1] = make_float2(w.x * dr - w.y * di, w.x * di + w.y * dr);
        __syncthreads();
        float2* tmp = A; A = Bf; Bf = tmp;
    }
    size_t base = (size_t)p * 65536 + (size_t)i * 256;
    d_Ym[base + t] = A[t];
    d_Ym[base + t + 128] = A[t + 128];
}

// ---------------- K6m: mask column IFFT ----------------
__global__ void k6m_col() {
    __shared__ float2 tA[8 * 257];
    __shared__ float2 tB[8 * 257];
    __shared__ float2 tw[128];
    int p = blockIdx.x >> 5;
    int jt = blockIdx.x & 31;
    int j0 = jt * 8;
    int t = threadIdx.x;  // 256
    if (t < 128) tw[t] = d_tw[t];
    int c = t & 7;
    int ib = t >> 3;
    size_t ybase = (size_t)p * 65536;

#pragma unroll
    for (int r = 0; r < 8; r++) {
        int i = ib + r * 32;
        tA[c * 257 + i] = d_Ym[ybase + (size_t)i * 256 + j0 + c];
    }
    __syncthreads();

    float2* A = tA;
    float2* Bf = tB;
#pragma unroll
    for (int s = 0; s < 8; s++) {
        int m1 = (1 << s) - 1;
#pragma unroll
        for (int u = 0; u < 4; u++) {
            int bf = t + u * 256;
            int col = bf >> 7;
            int tt = bf & 127;
            int k = tt & m1;
            int jm = tt - k;
            float2 c0 = A[col * 257 + tt];
            float2 c1 = A[col * 257 + tt + 128];
            float2 w = tw[jm];
            float dr = c0.x - c1.x, di = c0.y - c1.y;
            int lo = 2 * jm + k;
            Bf[col * 257 + lo] = make_float2(c0.x + c1.x, c0.y + c1.y);
            Bf[col * 257 + lo + m1 + 1] =
                make_float2(w.x * dr - w.y * di, w.x * di + w.y * dr);
        }
        __syncthreads();
        float2* tmp = A; A = Bf; Bf = tmp;
    }
#pragma unroll
    for (int r = 0; r < 8; r++) {
        int i = ib + r * 32;
        d_M[ybase + (size_t)i * 256 + j0 + c] = A[c * 257 + i];
    }
}

// ---------------- K7: combine 24 masks over 64 (b,c), magnitude + 2x2 pool ----------------
__global__ void k7_combine(const float* __restrict__ x, float* __restrict__ out) {
    __shared__ float2 sCp[64 * 24];
    int i = blockIdx.x;          // row 0..255
    int j = threadIdx.x;         // col 0..255
    int pix = i * 256 + j;

    for (int e = threadIdx.x; e < 64 * 24; e += 256) sCp[e] = d_Cp[e];

    float Mr[24], Mi[24];
#pragma unroll
    for (int p = 0; p < 24; p++) {
        float2 m = d_M[(size_t)p * 65536 + pix];
        Mr[p] = m.x;
        Mi[p] = m.y;
    }
    __syncthreads();

    size_t xrow0 = (size_t)(2 * i) * 512 + 2 * j;   // per-channel offsets
    size_t xrow1 = xrow0 + 512;

#pragma unroll 2
    for (int bc = 0; bc < 64; bc++) {
        float ar = 0.f, ai = 0.f;
#pragma unroll
        for (int p = 0; p < 24; p++) {
            float2 cp = sCp[bc * 24 + p];
            ar = fmaf(cp.x, Mr[p], ar);
            ar = fmaf(-cp.y, Mi[p], ar);
            ai = fmaf(cp.x, Mi[p], ai);
            ai = fmaf(cp.y, Mr[p], ai);
        }
        float mag = sqrtf(ar * ar + ai * ai);
        const float* xb = x + (size_t)bc * 262144;
        float2 a0 = *(const float2*)(xb + xrow0);
        float2 a1 = *(const float2*)(xb + xrow1);
        out[(size_t)bc * 65536 + pix] = mag + 0.25f * (a0.x + a0.y + a1.x + a1.y);
    }
}

// ---------------- launch ----------------
extern "C" void kernel_launch(void* const* d_in, const int* in_sizes, int n_in,
                              void* d_out, int out_size) {
    const float* x   = (const float*)d_in[0];
    const int*   ei  = (const int*)d_in[1];
    const float* w1r = (const float*)d_in[2];
    const float* b1r = (const float*)d_in[3];
    const float* w2r = (const float*)d_in[4];
    const float* b2r = (const float*)d_in[5];
    const float* w1i = (const float*)d_in[6];
    const float* b1i = (const float*)d_in[7];
    const float* w2i = (const float*)d_in[8];
    const float* b2i = (const float*)d_in[9];
    float* out = (float*)d_out;

    k0_colpart<<<dim3(8, 2), 512>>>(x);
    k1_tables<<<1, 256>>>(w1r, b1r, w2r, b2r, w1i, b1i, w2i, b2i);
    k4_tw<<<1, 128>>>();
    klut<<<1, 32>>>();
    k2_cp<<<64, 64>>>();
    k3_pix<<<256, 256>>>(ei);
    k5m_row<<<24 * 256, 128>>>();
    k6m_col<<<24 * 32, 256>>>();
    k7_combine<<<256, 256>>>(x, out);
}

// round 5
// speedup vs baseline: 1.0642x; 1.0642x over previous
#include <cuda_runtime.h>
#include <math.h>

// B=2, C=32, H=512, W=512, SCALE=2 -> Hs=Ws=256, S2=4
// Structure: argsort indices are permutations of {0..3} -> 24 distinct codes.
// ifft2 linear => per (b,c): ifft2(X) = sum_p Cp[bc][p] * M_p, M_p = ifft2(mask_p).
// Masks are real -> pack pairs (2q,2q+1) into one complex IFFT (12 planes), and
// M(-u) = conj(M(u)) -> one thread produces two output pixels from shared accums.

// ---------------- scratch ----------------
__device__ float         d_Fpart[2 * 8 * 8];
__device__ float2        d_Cp[64 * 24];            // (Cr,Ci) per (bc,perm), scaled
__device__ unsigned char d_ppix[256 * 256];        // per-pixel perm index [0,24)
__device__ float2        d_Ym[12 * 256 * 256];     // row-IFFT intermediate (6.3MB)
__device__ float2        d_W[12 * 256 * 256];      // packed-pair 2D IFFT (6.3MB)

// ---------------- f32x2 helpers ----------------
__device__ __forceinline__ unsigned long long pk2(float lo, float hi) {
    unsigned long long r;
    asm("mov.b64 %0, {%1, %2};" : "=l"(r) : "f"(lo), "f"(hi));
    return r;
}
__device__ __forceinline__ void upk2(unsigned long long v, float& lo, float& hi) {
    asm("mov.b64 {%0, %1}, %2;" : "=f"(lo), "=f"(hi) : "l"(v));
}
__device__ __forceinline__ unsigned long long ffma2(unsigned long long a,
                                                    unsigned long long b,
                                                    unsigned long long c) {
    unsigned long long r;
    asm("fma.rn.f32x2 %0, %1, %2, %3;" : "=l"(r) : "l"(a), "l"(b), "l"(c));
    return r;
}

// permutation unranking; code packs perm elems at 2-bit fields
__device__ __forceinline__ int perm_code(int p) {
    int avail[4] = {0, 1, 2, 3};
    const int f[3] = {6, 2, 1};
    int code = 0, rem = p;
#pragma unroll
    for (int pos = 0; pos < 3; pos++) {
        int sel = rem / f[pos];
        rem -= sel * f[pos];
        int e = avail[sel];
#pragma unroll
        for (int q = 0; q < 3; q++)
            if (q >= sel) avail[q] = avail[q + 1];
        code |= e << (2 * pos);
    }
    code |= avail[0] << 6;
    return code;
}

// ---------------- KA: fused (k0 column partial sums) + (k3 pixel perm ids) ----------------
__global__ void kA(const float* __restrict__ x, const int* __restrict__ ei) {
    int blk = blockIdx.x;
    if (blk < 16) {
        // k0 part: F[b,t] partial sums over 64-row slabs, channel 0
        int b = blk >> 3, hb = blk & 7;
        int w = threadIdx.x;  // 512
        const float* xp = x + (size_t)b * 32 * 512 * 512 + (size_t)(hb * 64) * 512 + w;
        float s = 0.f;
#pragma unroll 8
        for (int h = 0; h < 64; h++) s += xp[(size_t)h * 512];

        float vals[8];
#pragma unroll
        for (int t = 0; t < 4; t++) {
            float ph = (float)(t * w) * (1.0f / 256.0f);
            float sn, cs;
            sincospif(ph, &sn, &cs);
            vals[2 * t] = s * cs;
            vals[2 * t + 1] = -s * sn;
        }
        unsigned lane = threadIdx.x & 31, wid = threadIdx.x >> 5;
#pragma unroll
        for (int v = 0; v < 8; v++)
#pragma unroll
            for (int off = 16; off; off >>= 1)
                vals[v] += __shfl_down_sync(0xffffffff, vals[v], off);
        __shared__ float wsum[16][8];
        if (lane == 0)
            for (int v = 0; v < 8; v++) wsum[wid][v] = vals[v];
        __syncthreads();
        if (threadIdx.x == 0) {
            for (int v = 0; v < 8; v++) {
                float a = 0.f;
                for (int k = 0; k < 16; k++) a += wsum[k][v];
                d_Fpart[(b * 8 + hb) * 8 + v] = a;
            }
        }
    } else {
        // k3 part: per-pixel perm index, with local code->perm LUT
        __shared__ unsigned char lut[256];
        if (threadIdx.x < 24) lut[perm_code(threadIdx.x)] = (unsigned char)threadIdx.x;
        __syncthreads();
        int pix = (blk - 16) * 512 + threadIdx.x;
        unsigned code = 0;
#pragma unroll
        for (int P = 0; P < 4; P++)
            code |= ((unsigned)ei[(size_t)P * 2097152 + pix] & 3u) << (2 * P);
        d_ppix[pix] = lut[code];
    }
}

// ---------------- KB: F reduce + MLP tables + softmax-combined Cp ----------------
__global__ void kB(const float* __restrict__ w1r, const float* __restrict__ b1r,
                   const float* __restrict__ w2r, const float* __restrict__ b2r,
                   const float* __restrict__ w1i, const float* __restrict__ b1i,
                   const float* __restrict__ w2i, const float* __restrict__ b2i) {
    __shared__ float2 sF[8];
    __shared__ float sTR[1024], sTI[1024];
    int tid = threadIdx.x;  // 256
    if (tid < 8) {
        int b = tid >> 2, k = tid & 3;
        float re = 0.f, im = 0.f;
        for (int hb = 0; hb < 8; hb++) {
            re += d_Fpart[(b * 8 + hb) * 8 + 2 * k];
            im += d_Fpart[(b * 8 + hb) * 8 + 2 * k + 1];
        }
        sF[tid] = make_float2(re, im);
    }
    __syncthreads();

    for (int e = tid; e < 2048; e += 256) {
        int isI = e >> 10;
        int r = e & 1023;
        int b = r >> 9;
        int g = (r >> 4) & 31;
        int o = (r >> 2) & 3;
        int k = r & 3;
        const float* w1 = isI ? w1i : w1r;
        const float* b1 = isI ? b1i : b1r;
        const float* w2 = isI ? w2i : w2r;
        const float* b2 = isI ? b2i : b2r;
        float v = isI ? sF[b * 4 + k].y : sF[b * 4 + k].x;
        float h[4];
#pragma unroll
        for (int ii = 0; ii < 4; ii++) {
            const float* wrow = w1 + (g * 4 + ii) * 4;
            float ws = wrow[0] + wrow[1] + wrow[2] + wrow[3];
            float y = v * ws + b1[g * 4 + ii];
            h[ii] = y > 0.f ? y : 0.1f * y;
        }
        float out = b2[g * 4 + o];
#pragma unroll
        for (int ii = 0; ii < 4; ii++) out += w2[(g * 4 + o) * 4 + ii] * h[ii];
        (isI ? sTI : sTR)[r] = out;
    }
    __syncthreads();

    // 1536 outputs: e = bc*24 + p
    for (int e = tid; e < 1536; e += 256) {
        int bc = e / 24;
        int p = e - bc * 24;
        int b = bc >> 5, Cc = bc & 31;
        int code = perm_code(p);
        int ks[4] = { code & 3, (code >> 2) & 3, (code >> 4) & 3, (code >> 6) & 3 };
        float ar[4], ai[4];
#pragma unroll
        for (int P = 0; P < 4; P++) {
            int g = 8 * P + (Cc >> 2), o = Cc & 3;
            int idx = ((b * 32 + g) * 4 + o) * 4 + ks[P];
            ar[P] = sTR[idx & 1023];
            ai[P] = sTI[idx & 1023];
        }
        float mr = fmaxf(fmaxf(ar[0], ar[1]), fmaxf(ar[2], ar[3]));
        float mi = fmaxf(fmaxf(ai[0], ai[1]), fmaxf(ai[2], ai[3]));
        float er[4], ei_[4], sre = 0.f, sie = 0.f;
#pragma unroll
        for (int P = 0; P < 4; P++) {
            er[P] = __expf(ar[P] - mr); sre += er[P];
            ei_[P] = __expf(ai[P] - mi); sie += ei_[P];
        }
        float rinv = 1.f / sre, iinv = 1.f / sie;
        float Cr = 0.f, Ci = 0.f;
#pragma unroll
        for (int P = 0; P < 4; P++) {
            float sr = er[P] * rinv, si = ei_[P] * iinv;
            float fr = sF[b * 4 + ks[P]].x, fi = sF[b * 4 + ks[P]].y;
            Cr += fr * sr - fi * si;
            Ci += fr * si + fi * sr;
        }
        // fold ifft2 norm 1/65536 and the 1/2 from Hermitian pair reconstruction
        d_Cp[e] = make_float2(Cr * (1.f / 131072.f), Ci * (1.f / 131072.f));
    }
}

// ---------------- KC: pair-packed row IFFT (masks 2q + i*mask 2q+1) ----------------
__global__ void kC_row() {
    __shared__ float2 bufA[256], bufB[256];
    __shared__ float2 tw[128];
    int q = blockIdx.x >> 8;    // 0..11
    int i = blockIdx.x & 255;
    int t = threadIdx.x;        // 128

    {
        float sn, cs;
        sincospif((float)t * (1.0f / 128.0f), &sn, &cs);
        tw[t] = make_float2(cs, sn);
    }
    int m2q = 2 * q;
    unsigned char id0 = d_ppix[i * 256 + t];
    unsigned char id1 = d_ppix[i * 256 + t + 128];
    bufA[t] = make_float2(id0 == m2q ? 1.f : 0.f, id0 == m2q + 1 ? 1.f : 0.f);
    bufA[t + 128] = make_float2(id1 == m2q ? 1.f : 0.f, id1 == m2q + 1 ? 1.f : 0.f);
    __syncthreads();

    float2* A = bufA;
    float2* Bf = bufB;
#pragma unroll
    for (int s = 0; s < 8; s++) {
        int m1 = (1 << s) - 1;
        int k = t & m1;
        int jm = t - k;
        float2 c0 = A[t];
        float2 c1 = A[t + 128];
        float2 w = tw[jm];
        float dr = c0.x - c1.x, di = c0.y - c1.y;
        int lo = 2 * jm + k;
        Bf[lo] = make_float2(c0.x + c1.x, c0.y + c1.y);
        Bf[lo + m1 + 1] = make_float2(w.x * dr - w.y * di, w.x * di + w.y * dr);
        __syncthreads();
        float2* tmp = A; A = Bf; Bf = tmp;
    }
    size_t base = (size_t)q * 65536 + (size_t)i * 256;
    d_Ym[base + t] = A[t];
    d_Ym[base + t + 128] = A[t + 128];
}

// ---------------- KD: pair-packed column IFFT ----------------
__global__ void kD_col() {
    __shared__ float2 tA[8 * 257];
    __shared__ float2 tB[8 * 257];
    __shared__ float2 tw[128];
    int q = blockIdx.x >> 5;    // 0..11
    int jt = blockIdx.x & 31;
    int j0 = jt * 8;
    int t = threadIdx.x;        // 256
    if (t < 128) {
        float sn, cs;
        sincospif((float)t * (1.0f / 128.0f), &sn, &cs);
        tw[t] = make_float2(cs, sn);
    }
    int c = t & 7;
    int ib = t >> 3;
    size_t ybase = (size_t)q * 65536;

#pragma unroll
    for (int r = 0; r < 8; r++) {
        int i = ib + r * 32;
        tA[c * 257 + i] = d_Ym[ybase + (size_t)i * 256 + j0 + c];
    }
    __syncthreads();

    float2* A = tA;
    float2* Bf = tB;
#pragma unroll
    for (int s = 0; s < 8; s++) {
        int m1 = (1 << s) - 1;
#pragma unroll
        for (int u = 0; u < 4; u++) {
            int bf = t + u * 256;
            int col = bf >> 7;
            int tt = bf & 127;
            int k = tt & m1;
            int jm = tt - k;
            float2 c0 = A[col * 257 + tt];
            float2 c1 = A[col * 257 + tt + 128];
            float2 w = tw[jm];
            float dr = c0.x - c1.x, di = c0.y - c1.y;
            int lo = 2 * jm + k;
            Bf[col * 257 + lo] = make_float2(c0.x + c1.x, c0.y + c1.y);
            Bf[col * 257 + lo + m1 + 1] =
                make_float2(w.x * dr - w.y * di, w.x * di + w.y * dr);
        }
        __syncthreads();
        float2* tmp = A; A = Bf; Bf = tmp;
    }
#pragma unroll
    for (int r = 0; r < 8; r++) {
        int i = ib + r * 32;
        d_W[ybase + (size_t)i * 256 + j0 + c] = A[c * 257 + i];
    }
}

// ---------------- KE: combine; each thread emits pixel (i,j) AND (-i,-j) ----------------
__global__ void __launch_bounds__(256) kE_combine(const float* __restrict__ x,
                                                  float* __restrict__ out) {
    __shared__ unsigned long long sA[64 * 24];  // (Cr,Cr) packed
    __shared__ unsigned long long sB[64 * 24];  // (Ci,Ci) packed
    int i = blockIdx.x;          // 0..128
    int j = threadIdx.x;         // 0..255
    for (int e = threadIdx.x; e < 1536; e += 256) {
        float2 cp = d_Cp[e];
        sA[e] = pk2(cp.x, cp.x);
        sB[e] = pk2(cp.y, cp.y);
    }

    int im = (256 - i) & 255;
    int jm = (256 - j) & 255;
    int pix = i * 256 + j;
    int mir = im * 256 + jm;

    // Reconstruct the 24 real-mask IFFT values (x2, scale folded into Cp):
    // U[2q]   = ( Wr + Wpr,  Wi - Wpi )
    // U[2q+1] = ( Wi + Wpi,  Wpr - Wr )
    unsigned long long U[24];
#pragma unroll
    for (int q = 0; q < 12; q++) {
        float2 w = d_W[(size_t)q * 65536 + pix];
        float2 wp = d_W[(size_t)q * 65536 + mir];
        U[2 * q] = pk2(w.x + wp.x, w.y - wp.y);
        U[2 * q + 1] = pk2(w.y + wp.y, wp.x - w.x);
    }
    __syncthreads();

    size_t xr0 = (size_t)(2 * i) * 512 + 2 * j;
    size_t xr1 = xr0 + 512;
    size_t xm0 = (size_t)(2 * im) * 512 + 2 * jm;
    size_t xm1 = xm0 + 512;

    for (int bc = 0; bc < 64; bc++) {
        unsigned long long accA = 0ull, accB = 0ull;
        const unsigned long long* pA = &sA[bc * 24];
        const unsigned long long* pB = &sB[bc * 24];
#pragma unroll
        for (int p = 0; p < 24; p++) {
            accA = ffma2(pA[p], U[p], accA);
            accB = ffma2(pB[p], U[p], accB);
        }
        float a0, a1, b0, b1;
        upk2(accA, a0, a1);
        upk2(accB, b0, b1);
        // pixel (i,j):  val = (a0 - b1) + i(a1 + b0)
        // pixel (-i,-j): masks conjugate -> val' = (a0 + b1) + i(b0 - a1)
        float ar = a0 - b1, ai = a1 + b0;
        float ar2 = a0 + b1, ai2 = b0 - a1;
        float mag = sqrtf(ar * ar + ai * ai);
        float mag2 = sqrtf(ar2 * ar2 + ai2 * ai2);

        const float* xb = x + (size_t)bc * 262144;
        float2 p0 = *(const float2*)(xb + xr0);
        float2 p1 = *(const float2*)(xb + xr1);
        float2 q0 = *(const float2*)(xb + xm0);
        float2 q1 = *(const float2*)(xb + xm1);
        out[(size_t)bc * 65536 + pix] = mag + 0.25f * (p0.x + p0.y + p1.x + p1.y);
        out[(size_t)bc * 65536 + mir] = mag2 + 0.25f * (q0.x + q0.y + q1.x + q1.y);
    }
}

// ---------------- launch ----------------
extern "C" void kernel_launch(void* const* d_in, const int* in_sizes, int n_in,
                              void* d_out, int out_size) {
    const float* x   = (const float*)d_in[0];
    const int*   ei  = (const int*)d_in[1];
    const float* w1r = (const float*)d_in[2];
    const float* b1r = (const float*)d_in[3];
    const float* w2r = (const float*)d_in[4];
    const float* b2r = (const float*)d_in[5];
    const float* w1i = (const float*)d_in[6];
    const float* b1i = (const float*)d_in[7];
    const float* w2i = (const float*)d_in[8];
    const float* b2i = (const float*)d_in[9];
    float* out = (float*)d_out;

    kA<<<144, 512>>>(x, ei);
    kB<<<1, 256>>>(w1r, b1r, w2r, b2r, w1i, b1i, w2i, b2i);
    kC_row<<<12 * 256, 128>>>();
    kD_col<<<12 * 32, 256>>>();
    kE_combine<<<129, 256>>>(x, out);
}

// round 6
// speedup vs baseline: 1.1498x; 1.0805x over previous
#include <cuda_runtime.h>
#include <math.h>

// B=2, C=32, H=512, W=512, SCALE=2 -> Hs=Ws=256, S2=4
// argsort indices are permutations of {0..3} -> 24 distinct per-pixel codes.
// ifft2 linear => per (b,c): ifft2(X) = sum_p Cp[bc][p] * M_p, M_p = ifft2(mask_p).
// Masks real -> pack pairs (2q,2q+1) into 12 complex IFFT planes; M(-u)=conj(M(u))
// lets one thread emit two output pixels. FFTs are radix-4 Stockham (4 stages).

// ---------------- scratch ----------------
__device__ float         d_Fpart[2 * 8 * 8];
__device__ float2        d_Cp[64 * 24];
__device__ unsigned char d_ppix[256 * 256];
__device__ float2        d_Ym[12 * 256 * 256];     // row-IFFT intermediate (6.3MB)
__device__ float2        d_W[12 * 256 * 256];      // packed-pair 2D IFFT (6.3MB)

// ---------------- f32x2 helpers ----------------
__device__ __forceinline__ unsigned long long pk2(float lo, float hi) {
    unsigned long long r;
    asm("mov.b64 %0, {%1, %2};" : "=l"(r) : "f"(lo), "f"(hi));
    return r;
}
__device__ __forceinline__ void upk2(unsigned long long v, float& lo, float& hi) {
    asm("mov.b64 {%0, %1}, %2;" : "=f"(lo), "=f"(hi) : "l"(v));
}
__device__ __forceinline__ unsigned long long ffma2(unsigned long long a,
                                                    unsigned long long b,
                                                    unsigned long long c) {
    unsigned long long r;
    asm("fma.rn.f32x2 %0, %1, %2, %3;" : "=l"(r) : "l"(a), "l"(b), "l"(c));
    return r;
}

__device__ __forceinline__ float2 cmul(float2 w, float2 z) {
    return make_float2(w.x * z.x - w.y * z.y, w.x * z.y + w.y * z.x);
}

// permutation unranking; code packs perm elems at 2-bit fields
__device__ __forceinline__ int perm_code(int p) {
    int avail[4] = {0, 1, 2, 3};
    const int f[3] = {6, 2, 1};
    int code = 0, rem = p;
#pragma unroll
    for (int pos = 0; pos < 3; pos++) {
        int sel = rem / f[pos];
        rem -= sel * f[pos];
        int e = avail[sel];
#pragma unroll
        for (int q = 0; q < 3; q++)
            if (q >= sel) avail[q] = avail[q + 1];
        code |= e << (2 * pos);
    }
    code |= avail[0] << 6;
    return code;
}

// ---------------- KA: fused (column partial sums for F) + (pixel perm ids) ----------------
__global__ void kA(const float* __restrict__ x, const int* __restrict__ ei) {
    int blk = blockIdx.x;
    if (blk < 16) {
        int b = blk >> 3, hb = blk & 7;
        int w = threadIdx.x;  // 512
        const float* xp = x + (size_t)b * 32 * 512 * 512 + (size_t)(hb * 64) * 512 + w;
        float s = 0.f;
#pragma unroll 8
        for (int h = 0; h < 64; h++) s += xp[(size_t)h * 512];

        float vals[8];
#pragma unroll
        for (int t = 0; t < 4; t++) {
            float ph = (float)(t * w) * (1.0f / 256.0f);
            float sn, cs;
            sincospif(ph, &sn, &cs);
            vals[2 * t] = s * cs;
            vals[2 * t + 1] = -s * sn;
        }
        unsigned lane = threadIdx.x & 31, wid = threadIdx.x >> 5;
#pragma unroll
        for (int v = 0; v < 8; v++)
#pragma unroll
            for (int off = 16; off; off >>= 1)
                vals[v] += __shfl_down_sync(0xffffffff, vals[v], off);
        __shared__ float wsum[16][8];
        if (lane == 0)
            for (int v = 0; v < 8; v++) wsum[wid][v] = vals[v];
        __syncthreads();
        if (threadIdx.x == 0) {
            for (int v = 0; v < 8; v++) {
                float a = 0.f;
                for (int k = 0; k < 16; k++) a += wsum[k][v];
                d_Fpart[(b * 8 + hb) * 8 + v] = a;
            }
        }
    } else {
        __shared__ unsigned char lut[256];
        if (threadIdx.x < 24) lut[perm_code(threadIdx.x)] = (unsigned char)threadIdx.x;
        __syncthreads();
        int pix = (blk - 16) * 512 + threadIdx.x;
        unsigned code = 0;
#pragma unroll
        for (int P = 0; P < 4; P++)
            code |= ((unsigned)ei[(size_t)P * 2097152 + pix] & 3u) << (2 * P);
        d_ppix[pix] = lut[code];
    }
}

// ---------------- kB body (runs as the extra block of kC) ----------------
__device__ void kB_body(const float* __restrict__ w1r, const float* __restrict__ b1r,
                        const float* __restrict__ w2r, const float* __restrict__ b2r,
                        const float* __restrict__ w1i, const float* __restrict__ b1i,
                        const float* __restrict__ w2i, const float* __restrict__ b2i) {
    __shared__ float2 sF[8];
    __shared__ float sTR[1024], sTI[1024];
    int tid = threadIdx.x;  // 128
    if (tid < 8) {
        int b = tid >> 2, k = tid & 3;
        float re = 0.f, im = 0.f;
        for (int hb = 0; hb < 8; hb++) {
            re += d_Fpart[(b * 8 + hb) * 8 + 2 * k];
            im += d_Fpart[(b * 8 + hb) * 8 + 2 * k + 1];
        }
        sF[tid] = make_float2(re, im);
    }
    __syncthreads();

    for (int e = tid; e < 2048; e += 128) {
        int isI = e >> 10;
        int r = e & 1023;
        int b = r >> 9;
        int g = (r >> 4) & 31;
        int o = (r >> 2) & 3;
        int k = r & 3;
        const float* w1 = isI ? w1i : w1r;
        const float* b1 = isI ? b1i : b1r;
        const float* w2 = isI ? w2i : w2r;
        const float* b2 = isI ? b2i : b2r;
        float v = isI ? sF[b * 4 + k].y : sF[b * 4 + k].x;
        float h[4];
#pragma unroll
        for (int ii = 0; ii < 4; ii++) {
            const float* wrow = w1 + (g * 4 + ii) * 4;
            float ws = wrow[0] + wrow[1] + wrow[2] + wrow[3];
            float y = v * ws + b1[g * 4 + ii];
            h[ii] = y > 0.f ? y : 0.1f * y;
        }
        float out = b2[g * 4 + o];
#pragma unroll
        for (int ii = 0; ii < 4; ii++) out += w2[(g * 4 + o) * 4 + ii] * h[ii];
        (isI ? sTI : sTR)[r] = out;
    }
    __syncthreads();

    for (int e = tid; e < 1536; e += 128) {
        int bc = e / 24;
        int p = e - bc * 24;
        int b = bc >> 5, Cc = bc & 31;
        int code = perm_code(p);
        int ks[4] = { code & 3, (code >> 2) & 3, (code >> 4) & 3, (code >> 6) & 3 };
        float ar[4], ai[4];
#pragma unroll
        for (int P = 0; P < 4; P++) {
            int g = 8 * P + (Cc >> 2), o = Cc & 3;
            int idx = ((b * 32 + g) * 4 + o) * 4 + ks[P];
            ar[P] = sTR[idx & 1023];
            ai[P] = sTI[idx & 1023];
        }
        float mr = fmaxf(fmaxf(ar[0], ar[1]), fmaxf(ar[2], ar[3]));
        float mi = fmaxf(fmaxf(ai[0], ai[1]), fmaxf(ai[2], ai[3]));
        float er[4], ei_[4], sre = 0.f, sie = 0.f;
#pragma unroll
        for (int P = 0; P < 4; P++) {
            er[P] = __expf(ar[P] - mr); sre += er[P];
            ei_[P] = __expf(ai[P] - mi); sie += ei_[P];
        }
        float rinv = 1.f / sre, iinv = 1.f / sie;
        float Cr = 0.f, Ci = 0.f;
#pragma unroll
        for (int P = 0; P < 4; P++) {
            float sr = er[P] * rinv, si = ei_[P] * iinv;
            float fr = sF[b * 4 + ks[P]].x, fi = sF[b * 4 + ks[P]].y;
            Cr += fr * sr - fi * si;
            Ci += fr * si + fi * sr;
        }
        // fold ifft2 norm 1/65536 and the 1/2 from Hermitian pair reconstruction
        d_Cp[e] = make_float2(Cr * (1.f / 131072.f), Ci * (1.f / 131072.f));
    }
}

// ---------------- KC: pair-packed row IFFT, radix-4 Stockham (2 rows/block) + kB block --------
__global__ void __launch_bounds__(128) kC_row(
        const float* __restrict__ w1r, const float* __restrict__ b1r,
        const float* __restrict__ w2r, const float* __restrict__ b2r,
        const float* __restrict__ w1i, const float* __restrict__ b1i,
        const float* __restrict__ w2i, const float* __restrict__ b2i) {
    if (blockIdx.x == 1536) {
        kB_body(w1r, b1r, w2r, b2r, w1i, b1i, w2i, b2i);
        return;
    }
    __shared__ float2 bufA[2][256], bufB[2][256];
    __shared__ float2 tw[256];
    int q = blockIdx.x >> 7;      // 0..11
    int rp = blockIdx.x & 127;    // row pair
    int t = threadIdx.x;          // 0..127

    for (int n = t; n < 256; n += 128) {
        float sn, cs;
        sincospif((float)n * (1.0f / 128.0f), &sn, &cs);
        tw[n] = make_float2(cs, sn);   // exp(+2*pi*i*n/256)
    }
    int row = t >> 6;
    int tt = t & 63;
    int i = rp * 2 + row;
    int m2q = 2 * q;
#pragma unroll
    for (int r = 0; r < 4; r++) {
        unsigned char id = d_ppix[i * 256 + tt + 64 * r];
        bufA[row][tt + 64 * r] =
            make_float2(id == m2q ? 1.f : 0.f, id == m2q + 1 ? 1.f : 0.f);
    }
    __syncthreads();

    float2 (*A)[256] = bufA;
    float2 (*Bf)[256] = bufB;
#pragma unroll
    for (int s = 0; s < 4; s++) {
        int m = 1 << (2 * s);
        int k = tt & (m - 1);
        int jm = tt - k;          // j*m
        float2 c0 = A[row][tt];
        float2 c1 = A[row][tt + 64];
        float2 c2 = A[row][tt + 128];
        float2 c3 = A[row][tt + 192];
        float2 t0 = make_float2(c0.x + c2.x, c0.y + c2.y);
        float2 t1 = make_float2(c0.x - c2.x, c0.y - c2.y);
        float2 t2 = make_float2(c1.x + c3.x, c1.y + c3.y);
        float2 t3 = make_float2(c1.x - c3.x, c1.y - c3.y);
        float2 z0 = make_float2(t0.x + t2.x, t0.y + t2.y);
        float2 z2 = make_float2(t0.x - t2.x, t0.y - t2.y);
        float2 z1 = make_float2(t1.x - t3.y, t1.y + t3.x);   // t1 + i*t3
        float2 z3 = make_float2(t1.x + t3.y, t1.y - t3.x);   // t1 - i*t3
        int lo = 4 * jm + k;
        Bf[row][lo] = z0;
        Bf[row][lo + m] = cmul(tw[jm], z1);
        Bf[row][lo + 2 * m] = cmul(tw[2 * jm], z2);
        Bf[row][lo + 3 * m] = cmul(tw[3 * jm], z3);
        __syncthreads();
        float2 (*tmp)[256] = A; A = Bf; Bf = tmp;
    }
    size_t base = (size_t)q * 65536 + (size_t)i * 256;
#pragma unroll
    for (int r = 0; r < 4; r++)
        d_Ym[base + tt + 64 * r] = A[row][tt + 64 * r];
}

// ---------------- KD: pair-packed column IFFT, radix-4 Stockham ----------------
__global__ void __launch_bounds__(256) kD_col() {
    __shared__ float2 tA[8 * 257];
    __shared__ float2 tB[8 * 257];
    __shared__ float2 tw[256];
    int q = blockIdx.x >> 5;
    int jt = blockIdx.x & 31;
    int j0 = jt * 8;
    int t = threadIdx.x;  // 256
    {
        float sn, cs;
        sincospif((float)t * (1.0f / 128.0f), &sn, &cs);
        tw[t] = make_float2(cs, sn);
    }
    int c = t & 7;
    int ib = t >> 3;
    size_t ybase = (size_t)q * 65536;

#pragma unroll
    for (int r = 0; r < 8; r++) {
        int i = ib + r * 32;
        tA[c * 257 + i] = d_Ym[ybase + (size_t)i * 256 + j0 + c];
    }
    __syncthreads();

    float2* A = tA;
    float2* Bf = tB;
#pragma unroll
    for (int s = 0; s < 4; s++) {
        int m = 1 << (2 * s);
#pragma unroll
        for (int u = 0; u < 2; u++) {
            int bf = t + u * 256;     // 0..511
            int col = bf >> 6;        // 0..7
            int tt = bf & 63;
            int k = tt & (m - 1);
            int jm = tt - k;
            float2 c0 = A[col * 257 + tt];
            float2 c1 = A[col * 257 + tt + 64];
            float2 c2 = A[col * 257 + tt + 128];
            float2 c3 = A[col * 257 + tt + 192];
            float2 t0 = make_float2(c0.x + c2.x, c0.y + c2.y);
            float2 t1 = make_float2(c0.x - c2.x, c0.y - c2.y);
            float2 t2 = make_float2(c1.x + c3.x, c1.y + c3.y);
            float2 t3 = make_float2(c1.x - c3.x, c1.y - c3.y);
            float2 z0 = make_float2(t0.x + t2.x, t0.y + t2.y);
            float2 z2 = make_float2(t0.x - t2.x, t0.y - t2.y);
            float2 z1 = make_float2(t1.x - t3.y, t1.y + t3.x);
            float2 z3 = make_float2(t1.x + t3.y, t1.y - t3.x);
            int lo = col * 257 + 4 * jm + k;
            Bf[lo] = z0;
            Bf[lo + m] = cmul(tw[jm], z1);
            Bf[lo + 2 * m] = cmul(tw[2 * jm], z2);
            Bf[lo + 3 * m] = cmul(tw[3 * jm], z3);
        }
        __syncthreads();
        float2* tmp = A; A = Bf; Bf = tmp;
    }
#pragma unroll
    for (int r = 0; r < 8; r++) {
        int i = ib + r * 32;
        d_W[ybase + (size_t)i * 256 + j0 + c] = A[c * 257 + i];
    }
}

// ---------------- KE: combine; each thread emits pixel (i,j) AND (-i,-j) ----------------
__global__ void __launch_bounds__(256) kE_combine(const float* __restrict__ x,
                                                  float* __restrict__ out) {
    __shared__ unsigned long long sA[64 * 24];  // (Cr,Cr) packed
    __shared__ unsigned long long sB[64 * 24];  // (Ci,Ci) packed
    int i = blockIdx.x;          // 0..128
    int j = threadIdx.x;         // 0..255
    for (int e = threadIdx.x; e < 1536; e += 256) {
        float2 cp = d_Cp[e];
        sA[e] = pk2(cp.x, cp.x);
        sB[e] = pk2(cp.y, cp.y);
    }

    int im = (256 - i) & 255;
    int jm = (256 - j) & 255;
    int pix = i * 256 + j;
    int mir = im * 256 + jm;

    // U[2q]   = ( Wr + Wpr,  Wi - Wpi )
    // U[2q+1] = ( Wi + Wpi,  Wpr - Wr )
    unsigned long long U[24];
#pragma unroll
    for (int q = 0; q < 12; q++) {
        float2 w = d_W[(size_t)q * 65536 + pix];
        float2 wp = d_W[(size_t)q * 65536 + mir];
        U[2 * q] = pk2(w.x + wp.x, w.y - wp.y);
        U[2 * q + 1] = pk2(w.y + wp.y, wp.x - w.x);
    }
    __syncthreads();

    size_t xr0 = (size_t)(2 * i) * 512 + 2 * j;
    size_t xr1 = xr0 + 512;
    size_t xm0 = (size_t)(2 * im) * 512 + 2 * jm;
    size_t xm1 = xm0 + 512;

    for (int bc = 0; bc < 64; bc++) {
        unsigned long long accA = 0ull, accB = 0ull;
        const unsigned long long* pA = &sA[bc * 24];
        const unsigned long long* pB = &sB[bc * 24];
#pragma unroll
        for (int p = 0; p < 24; p++) {
            accA = ffma2(pA[p], U[p], accA);
            accB = ffma2(pB[p], U[p], accB);
        }
        float a0, a1, b0, b1;
        upk2(accA, a0, a1);
        upk2(accB, b0, b1);
        float ar = a0 - b1, ai = a1 + b0;
        float ar2 = a0 + b1, ai2 = b0 - a1;
        float r2a = fmaxf(fmaf(ar, ar, ai * ai), 1e-38f);
        float r2b = fmaxf(fmaf(ar2, ar2, ai2 * ai2), 1e-38f);
        float mag = r2a * __frsqrt_rn(r2a);
        float mag2 = r2b * __frsqrt_rn(r2b);

        const float* xb = x + (size_t)bc * 262144;
        float2 p0 = *(const float2*)(xb + xr0);
        float2 p1 = *(const float2*)(xb + xr1);
        float2 q0 = *(const float2*)(xb + xm0);
        float2 q1 = *(const float2*)(xb + xm1);
        out[(size_t)bc * 65536 + pix] = mag + 0.25f * (p0.x + p0.y + p1.x + p1.y);
        out[(size_t)bc * 65536 + mir] = mag2 + 0.25f * (q0.x + q0.y + q1.x + q1.y);
    }
}

// ---------------- launch ----------------
extern "C" void kernel_launch(void* const* d_in, const int* in_sizes, int n_in,
                              void* d_out, int out_size) {
    const float* x   = (const float*)d_in[0];
    const int*   ei  = (const int*)d_in[1];
    const float* w1r = (const float*)d_in[2];
    const float* b1r = (const float*)d_in[3];
    const float* w2r = (const float*)d_in[4];
    const float* b2r = (const float*)d_in[5];
    const float* w1i = (const float*)d_in[6];
    const float* b1i = (const float*)d_in[7];
    const float* w2i = (const float*)d_in[8];
    const float* b2i = (const float*)d_in[9];
    float* out = (float*)d_out;

    kA<<<144, 512>>>(x, ei);
    kC_row<<<1537, 128>>>(w1r, b1r, w2r, b2r, w1i, b1i, w2i, b2i);
    kD_col<<<384, 256>>>();
    kE_combine<<<129, 256>>>(x, out);
}

// round 7
// speedup vs baseline: 1.4284x; 1.2423x over previous
#include <cuda_runtime.h>
#include <math.h>

// B=2, C=32, H=512, W=512, SCALE=2 -> Hs=Ws=256, S2=4
// argsort indices are permutations of {0..3} -> 24 distinct per-pixel codes.
// ifft2 linear => per (b,c): ifft2(X) = sum_p Cp[bc][p] * M_p, M_p = ifft2(mask_p).
// Masks real -> pack pairs (2q,2q+1) into 12 complex IFFT planes; M(-u)=conj(M(u))
// lets one thread emit two output pixels. FFTs are radix-4 Stockham (4 stages).
// kE parallelized over (row, bc-chunk) to fix grid starvation.

// ---------------- scratch ----------------
__device__ float         d_Fpart[2 * 8 * 8];
__device__ float2        d_Cp[64 * 24];
__device__ unsigned char d_ppix[256 * 256];
__device__ float2        d_Ym[12 * 256 * 256];     // row-IFFT intermediate (6.3MB)
__device__ float2        d_W[12 * 256 * 256];      // packed-pair 2D IFFT (6.3MB)

// ---------------- f32x2 helpers ----------------
__device__ __forceinline__ unsigned long long pk2(float lo, float hi) {
    unsigned long long r;
    asm("mov.b64 %0, {%1, %2};" : "=l"(r) : "f"(lo), "f"(hi));
    return r;
}
__device__ __forceinline__ void upk2(unsigned long long v, float& lo, float& hi) {
    asm("mov.b64 {%0, %1}, %2;" : "=f"(lo), "=f"(hi) : "l"(v));
}
__device__ __forceinline__ unsigned long long ffma2(unsigned long long a,
                                                    unsigned long long b,
                                                    unsigned long long c) {
    unsigned long long r;
    asm("fma.rn.f32x2 %0, %1, %2, %3;" : "=l"(r) : "l"(a), "l"(b), "l"(c));
    return r;
}

__device__ __forceinline__ float2 cmul(float2 w, float2 z) {
    return make_float2(w.x * z.x - w.y * z.y, w.x * z.y + w.y * z.x);
}

// permutation unranking; code packs perm elems at 2-bit fields
__device__ __forceinline__ int perm_code(int p) {
    int avail[4] = {0, 1, 2, 3};
    const int f[3] = {6, 2, 1};
    int code = 0, rem = p;
#pragma unroll
    for (int pos = 0; pos < 3; pos++) {
        int sel = rem / f[pos];
        rem -= sel * f[pos];
        int e = avail[sel];
#pragma unroll
        for (int q = 0; q < 3; q++)
            if (q >= sel) avail[q] = avail[q + 1];
        code |= e << (2 * pos);
    }
    code |= avail[0] << 6;
    return code;
}

// ---------------- KA: fused (column partial sums for F) + (pixel perm ids) ----------------
__global__ void kA(const float* __restrict__ x, const int* __restrict__ ei) {
    int blk = blockIdx.x;
    if (blk < 16) {
        int b = blk >> 3, hb = blk & 7;
        int w = threadIdx.x;  // 512
        const float* xp = x + (size_t)b * 32 * 512 * 512 + (size_t)(hb * 64) * 512 + w;
        float s = 0.f;
#pragma unroll 8
        for (int h = 0; h < 64; h++) s += xp[(size_t)h * 512];

        float vals[8];
#pragma unroll
        for (int t = 0; t < 4; t++) {
            float ph = (float)(t * w) * (1.0f / 256.0f);
            float sn, cs;
            sincospif(ph, &sn, &cs);
            vals[2 * t] = s * cs;
            vals[2 * t + 1] = -s * sn;
        }
        unsigned lane = threadIdx.x & 31, wid = threadIdx.x >> 5;
#pragma unroll
        for (int v = 0; v < 8; v++)
#pragma unroll
            for (int off = 16; off; off >>= 1)
                vals[v] += __shfl_down_sync(0xffffffff, vals[v], off);
        __shared__ float wsum[16][8];
        if (lane == 0)
            for (int v = 0; v < 8; v++) wsum[wid][v] = vals[v];
        __syncthreads();
        if (threadIdx.x == 0) {
            for (int v = 0; v < 8; v++) {
                float a = 0.f;
                for (int k = 0; k < 16; k++) a += wsum[k][v];
                d_Fpart[(b * 8 + hb) * 8 + v] = a;
            }
        }
    } else {
        __shared__ unsigned char lut[256];
        if (threadIdx.x < 24) lut[perm_code(threadIdx.x)] = (unsigned char)threadIdx.x;
        __syncthreads();
        int pix = (blk - 16) * 512 + threadIdx.x;
        unsigned code = 0;
#pragma unroll
        for (int P = 0; P < 4; P++)
            code |= ((unsigned)ei[(size_t)P * 2097152 + pix] & 3u) << (2 * P);
        d_ppix[pix] = lut[code];
    }
}

// ---------------- kB body (runs as the extra block of kC) ----------------
__device__ void kB_body(const float* __restrict__ w1r, const float* __restrict__ b1r,
                        const float* __restrict__ w2r, const float* __restrict__ b2r,
                        const float* __restrict__ w1i, const float* __restrict__ b1i,
                        const float* __restrict__ w2i, const float* __restrict__ b2i) {
    __shared__ float2 sF[8];
    __shared__ float sTR[1024], sTI[1024];
    int tid = threadIdx.x;  // 128
    if (tid < 8) {
        int b = tid >> 2, k = tid & 3;
        float re = 0.f, im = 0.f;
        for (int hb = 0; hb < 8; hb++) {
            re += d_Fpart[(b * 8 + hb) * 8 + 2 * k];
            im += d_Fpart[(b * 8 + hb) * 8 + 2 * k + 1];
        }
        sF[tid] = make_float2(re, im);
    }
    __syncthreads();

    for (int e = tid; e < 2048; e += 128) {
        int isI = e >> 10;
        int r = e & 1023;
        int b = r >> 9;
        int g = (r >> 4) & 31;
        int o = (r >> 2) & 3;
        int k = r & 3;
        const float* w1 = isI ? w1i : w1r;
        const float* b1 = isI ? b1i : b1r;
        const float* w2 = isI ? w2i : w2r;
        const float* b2 = isI ? b2i : b2r;
        float v = isI ? sF[b * 4 + k].y : sF[b * 4 + k].x;
        float h[4];
#pragma unroll
        for (int ii = 0; ii < 4; ii++) {
            const float* wrow = w1 + (g * 4 + ii) * 4;
            float ws = wrow[0] + wrow[1] + wrow[2] + wrow[3];
            float y = v * ws + b1[g * 4 + ii];
            h[ii] = y > 0.f ? y : 0.1f * y;
        }
        float out = b2[g * 4 + o];
#pragma unroll
        for (int ii = 0; ii < 4; ii++) out += w2[(g * 4 + o) * 4 + ii] * h[ii];
        (isI ? sTI : sTR)[r] = out;
    }
    __syncthreads();

    for (int e = tid; e < 1536; e += 128) {
        int bc = e / 24;
        int p = e - bc * 24;
        int b = bc >> 5, Cc = bc & 31;
        int code = perm_code(p);
        int ks[4] = { code & 3, (code >> 2) & 3, (code >> 4) & 3, (code >> 6) & 3 };
        float ar[4], ai[4];
#pragma unroll
        for (int P = 0; P < 4; P++) {
            int g = 8 * P + (Cc >> 2), o = Cc & 3;
            int idx = ((b * 32 + g) * 4 + o) * 4 + ks[P];
            ar[P] = sTR[idx & 1023];
            ai[P] = sTI[idx & 1023];
        }
        float mr = fmaxf(fmaxf(ar[0], ar[1]), fmaxf(ar[2], ar[3]));
        float mi = fmaxf(fmaxf(ai[0], ai[1]), fmaxf(ai[2], ai[3]));
        float er[4], ei_[4], sre = 0.f, sie = 0.f;
#pragma unroll
        for (int P = 0; P < 4; P++) {
            er[P] = __expf(ar[P] - mr); sre += er[P];
            ei_[P] = __expf(ai[P] - mi); sie += ei_[P];
        }
        float rinv = 1.f / sre, iinv = 1.f / sie;
        float Cr = 0.f, Ci = 0.f;
#pragma unroll
        for (int P = 0; P < 4; P++) {
            float sr = er[P] * rinv, si = ei_[P] * iinv;
            float fr = sF[b * 4 + ks[P]].x, fi = sF[b * 4 + ks[P]].y;
            Cr += fr * sr - fi * si;
            Ci += fr * si + fi * sr;
        }
        // fold ifft2 norm 1/65536 and the 1/2 from Hermitian pair reconstruction
        d_Cp[e] = make_float2(Cr * (1.f / 131072.f), Ci * (1.f / 131072.f));
    }
}

// ---------------- KC: pair-packed row IFFT, radix-4 Stockham (2 rows/block) + kB block --------
__global__ void __launch_bounds__(128) kC_row(
        const float* __restrict__ w1r, const float* __restrict__ b1r,
        const float* __restrict__ w2r, const float* __restrict__ b2r,
        const float* __restrict__ w1i, const float* __restrict__ b1i,
        const float* __restrict__ w2i, const float* __restrict__ b2i) {
    if (blockIdx.x == 1536) {
        kB_body(w1r, b1r, w2r, b2r, w1i, b1i, w2i, b2i);
        return;
    }
    __shared__ float2 bufA[2][256], bufB[2][256];
    __shared__ float2 tw[256];
    int q = blockIdx.x >> 7;      // 0..11
    int rp = blockIdx.x & 127;    // row pair
    int t = threadIdx.x;          // 0..127

    for (int n = t; n < 256; n += 128) {
        float sn, cs;
        sincospif((float)n * (1.0f / 128.0f), &sn, &cs);
        tw[n] = make_float2(cs, sn);   // exp(+2*pi*i*n/256)
    }
    int row = t >> 6;
    int tt = t & 63;
    int i = rp * 2 + row;
    int m2q = 2 * q;
#pragma unroll
    for (int r = 0; r < 4; r++) {
        unsigned char id = d_ppix[i * 256 + tt + 64 * r];
        bufA[row][tt + 64 * r] =
            make_float2(id == m2q ? 1.f : 0.f, id == m2q + 1 ? 1.f : 0.f);
    }
    __syncthreads();

    float2 (*A)[256] = bufA;
    float2 (*Bf)[256] = bufB;
#pragma unroll
    for (int s = 0; s < 4; s++) {
        int m = 1 << (2 * s);
        int k = tt & (m - 1);
        int jm = tt - k;          // j*m
        float2 c0 = A[row][tt];
        float2 c1 = A[row][tt + 64];
        float2 c2 = A[row][tt + 128];
        float2 c3 = A[row][tt + 192];
        float2 t0 = make_float2(c0.x + c2.x, c0.y + c2.y);
        float2 t1 = make_float2(c0.x - c2.x, c0.y - c2.y);
        float2 t2 = make_float2(c1.x + c3.x, c1.y + c3.y);
        float2 t3 = make_float2(c1.x - c3.x, c1.y - c3.y);
        float2 z0 = make_float2(t0.x + t2.x, t0.y + t2.y);
        float2 z2 = make_float2(t0.x - t2.x, t0.y - t2.y);
        float2 z1 = make_float2(t1.x - t3.y, t1.y + t3.x);   // t1 + i*t3
        float2 z3 = make_float2(t1.x + t3.y, t1.y - t3.x);   // t1 - i*t3
        int lo = 4 * jm + k;
        Bf[row][lo] = z0;
        Bf[row][lo + m] = cmul(tw[jm], z1);
        Bf[row][lo + 2 * m] = cmul(tw[2 * jm], z2);
        Bf[row][lo + 3 * m] = cmul(tw[3 * jm], z3);
        __syncthreads();
        float2 (*tmp)[256] = A; A = Bf; Bf = tmp;
    }
    size_t base = (size_t)q * 65536 + (size_t)i * 256;
#pragma unroll
    for (int r = 0; r < 4; r++)
        d_Ym[base + tt + 64 * r] = A[row][tt + 64 * r];
}

// ---------------- KD: pair-packed column IFFT, radix-4 Stockham ----------------
__global__ void __launch_bounds__(256) kD_col() {
    __shared__ float2 tA[8 * 257];
    __shared__ float2 tB[8 * 257];
    __shared__ float2 tw[256];
    int q = blockIdx.x >> 5;
    int jt = blockIdx.x & 31;
    int j0 = jt * 8;
    int t = threadIdx.x;  // 256
    {
        float sn, cs;
        sincospif((float)t * (1.0f / 128.0f), &sn, &cs);
        tw[t] = make_float2(cs, sn);
    }
    int c = t & 7;
    int ib = t >> 3;
    size_t ybase = (size_t)q * 65536;

#pragma unroll
    for (int r = 0; r < 8; r++) {
        int i = ib + r * 32;
        tA[c * 257 + i] = d_Ym[ybase + (size_t)i * 256 + j0 + c];
    }
    __syncthreads();

    float2* A = tA;
    float2* Bf = tB;
#pragma unroll
    for (int s = 0; s < 4; s++) {
        int m = 1 << (2 * s);
#pragma unroll
        for (int u = 0; u < 2; u++) {
            int bf = t + u * 256;     // 0..511
            int col = bf >> 6;        // 0..7
            int tt = bf & 63;
            int k = tt & (m - 1);
            int jm = tt - k;
            float2 c0 = A[col * 257 + tt];
            float2 c1 = A[col * 257 + tt + 64];
            float2 c2 = A[col * 257 + tt + 128];
            float2 c3 = A[col * 257 + tt + 192];
            float2 t0 = make_float2(c0.x + c2.x, c0.y + c2.y);
            float2 t1 = make_float2(c0.x - c2.x, c0.y - c2.y);
            float2 t2 = make_float2(c1.x + c3.x, c1.y + c3.y);
            float2 t3 = make_float2(c1.x - c3.x, c1.y - c3.y);
            float2 z0 = make_float2(t0.x + t2.x, t0.y + t2.y);
            float2 z2 = make_float2(t0.x - t2.x, t0.y - t2.y);
            float2 z1 = make_float2(t1.x - t3.y, t1.y + t3.x);
            float2 z3 = make_float2(t1.x + t3.y, t1.y - t3.x);
            int lo = col * 257 + 4 * jm + k;
            Bf[lo] = z0;
            Bf[lo + m] = cmul(tw[jm], z1);
            Bf[lo + 2 * m] = cmul(tw[2 * jm], z2);
            Bf[lo + 3 * m] = cmul(tw[3 * jm], z3);
        }
        __syncthreads();
        float2* tmp = A; A = Bf; Bf = tmp;
    }
#pragma unroll
    for (int r = 0; r < 8; r++) {
        int i = ib + r * 32;
        d_W[ybase + (size_t)i * 256 + j0 + c] = A[c * 257 + i];
    }
}

// ---------------- KE: combine over an 8-bc chunk; thread emits pixel (i,j) AND (-i,-j) --------
__global__ void __launch_bounds__(256) kE_combine(const float* __restrict__ x,
                                                  float* __restrict__ out) {
    __shared__ unsigned long long sA[8 * 24];  // (Cr,Cr) packed, this chunk
    __shared__ unsigned long long sB[8 * 24];  // (Ci,Ci) packed
    int i = blockIdx.x;          // 0..128
    int bc0 = blockIdx.y * 8;    // bc chunk base
    int j = threadIdx.x;         // 0..255
    if (threadIdx.x < 192) {
        float2 cp = d_Cp[bc0 * 24 + threadIdx.x];
        sA[threadIdx.x] = pk2(cp.x, cp.x);
        sB[threadIdx.x] = pk2(cp.y, cp.y);
    }

    int im = (256 - i) & 255;
    int jm = (256 - j) & 255;
    int pix = i * 256 + j;
    int mir = im * 256 + jm;

    // U[2q]   = ( Wr + Wpr,  Wi - Wpi )
    // U[2q+1] = ( Wi + Wpi,  Wpr - Wr )
    unsigned long long U[24];
#pragma unroll
    for (int q = 0; q < 12; q++) {
        float2 w = d_W[(size_t)q * 65536 + pix];
        float2 wp = d_W[(size_t)q * 65536 + mir];
        U[2 * q] = pk2(w.x + wp.x, w.y - wp.y);
        U[2 * q + 1] = pk2(w.y + wp.y, wp.x - w.x);
    }
    __syncthreads();

    size_t xr0 = (size_t)(2 * i) * 512 + 2 * j;
    size_t xr1 = xr0 + 512;
    size_t xm0 = (size_t)(2 * im) * 512 + 2 * jm;
    size_t xm1 = xm0 + 512;

#pragma unroll
    for (int k = 0; k < 8; k++) {
        int bc = bc0 + k;
        const unsigned long long* pA = &sA[k * 24];
        const unsigned long long* pB = &sB[k * 24];
        // two independent chains per accumulator to halve RAW latency
        unsigned long long a0 = 0ull, a1 = 0ull, b0 = 0ull, b1 = 0ull;
#pragma unroll
        for (int p = 0; p < 12; p++) {
            a0 = ffma2(pA[2 * p], U[2 * p], a0);
            a1 = ffma2(pA[2 * p + 1], U[2 * p + 1], a1);
            b0 = ffma2(pB[2 * p], U[2 * p], b0);
            b1 = ffma2(pB[2 * p + 1], U[2 * p + 1], b1);
        }
        float a0l, a0h, a1l, a1h, b0l, b0h, b1l, b1h;
        upk2(a0, a0l, a0h); upk2(a1, a1l, a1h);
        upk2(b0, b0l, b0h); upk2(b1, b1l, b1h);
        float sa0 = a0l + a1l, sa1 = a0h + a1h;   // accA = (Re-part dot) for px, mir
        float sb0 = b0l + b1l, sb1 = b0h + b1h;   // accB = (Im-coef dot)
        // pixel (i,j):   val = (sa0 - sb1) + i(sa1 + sb0)
        // pixel (-i,-j): val' = (sa0 + sb1) + i(sb0 - sa1)
        float ar = sa0 - sb1, ai = sa1 + sb0;
        float ar2 = sa0 + sb1, ai2 = sb0 - sa1;
        float r2a = fmaxf(fmaf(ar, ar, ai * ai), 1e-38f);
        float r2b = fmaxf(fmaf(ar2, ar2, ai2 * ai2), 1e-38f);
        float mag = r2a * __frsqrt_rn(r2a);
        float mag2 = r2b * __frsqrt_rn(r2b);

        const float* xb = x + (size_t)bc * 262144;
        float2 p0 = *(const float2*)(xb + xr0);
        float2 p1 = *(const float2*)(xb + xr1);
        float2 q0 = *(const float2*)(xb + xm0);
        float2 q1 = *(const float2*)(xb + xm1);
        out[(size_t)bc * 65536 + pix] = mag + 0.25f * (p0.x + p0.y + p1.x + p1.y);
        out[(size_t)bc * 65536 + mir] = mag2 + 0.25f * (q0.x + q0.y + q1.x + q1.y);
    }
}

// ---------------- launch ----------------
extern "C" void kernel_launch(void* const* d_in, const int* in_sizes, int n_in,
                              void* d_out, int out_size) {
    const float* x   = (const float*)d_in[0];
    const int*   ei  = (const int*)d_in[1];
    const float* w1r = (const float*)d_in[2];
    const float* b1r = (const float*)d_in[3];
    const float* w2r = (const float*)d_in[4];
    const float* b2r = (const float*)d_in[5];
    const float* w1i = (const float*)d_in[6];
    const float* b1i = (const float*)d_in[7];
    const float* w2i = (const float*)d_in[8];
    const float* b2i = (const float*)d_in[9];
    float* out = (float*)d_out;

    kA<<<144, 512>>>(x, ei);
    kC_row<<<1537, 128>>>(w1r, b1r, w2r, b2r, w1i, b1i, w2i, b2i);
    kD_col<<<384, 256>>>();
    kE_combine<<<dim3(129, 8), 256>>>(x, out);
}